// round 5
// baseline (speedup 1.0000x reference)
#include <cuda_runtime.h>
#include <cuda_bf16.h>
#include <cstdint>

// Problem constants (compile-time for __device__ scratch sizing)
constexpr int NN = 50000;   // nodes
constexpr int EE = 800000;  // edges
constexpr int F  = 128;     // feature dim

// ---------------- scratch (device globals; no allocation allowed) -----------
__device__ float g_tmp[NN * F];   // GEMM output  (h @ W)
__device__ float g_agg[NN * F];   // aggregation  (D^-1/2 (A+I) D^-1/2 · tmp)
__device__ float g_deg[NN];
__device__ float g_dis[NN];       // deg^{-1/2}

// ---------------- degree / normalization ------------------------------------
__global__ void init_deg_kernel(int n) {
    int i = blockIdx.x * blockDim.x + threadIdx.x;
    if (i < n) g_deg[i] = 1.0f;   // self-loop contributes 1 to every degree
}

__global__ void count_deg_kernel(const int* __restrict__ ei, int E) {
    int e = blockIdx.x * blockDim.x + threadIdx.x;
    if (e < E) atomicAdd(&g_deg[ei[E + e]], 1.0f);   // dst = ei[1][e]
}

__global__ void dis_kernel(int n) {
    int i = blockIdx.x * blockDim.x + threadIdx.x;
    if (i < n) g_dis[i] = rsqrtf(g_deg[i]);   // deg >= 1 always
}

// ---------------- GEMM: out = act(A) @ W  (A:[n,128], W:[128,128]) ----------
// BM=64 rows per CTA, 256 threads, each thread -> 8x4 outputs.
// A tile cached in smem (32 KB); W streamed via LDG (64 KB, L1/L2 resident).
// ELU(bias) of the PREVIOUS layer is fused into the A load.
__device__ __forceinline__ float elu_act(float v) {
    return v > 0.0f ? v : expm1f(v);
}

template <bool APPLY_ELU>
__global__ __launch_bounds__(256) void gemm_kernel(
    const float* __restrict__ Ain,   // nullptr => read g_agg
    const float* __restrict__ W,     // [128,128] row-major (k-major)
    const float* __restrict__ bias,  // [128] (prev layer bias) or nullptr
    int n)
{
    constexpr int BM = 64;
    __shared__ float sA[BM][F];

    const float* __restrict__ A = Ain ? Ain : g_agg;

    int tid  = threadIdx.x;
    int tidx = tid & 31;   // column group (4 cols)
    int tidy = tid >> 5;   // row group (8 rows) == warp id
    int rowBase = blockIdx.x * BM;

    // Load A tile: 64*128 floats = 2048 float4 slots, 8 per thread.
    #pragma unroll
    for (int t = 0; t < 8; t++) {
        int idx = t * 256 + tid;   // float4 slot
        int r   = idx >> 5;
        int c4  = idx & 31;
        int grow = rowBase + r;
        float4 v = make_float4(0.f, 0.f, 0.f, 0.f);
        if (grow < n)
            v = *(const float4*)(A + (size_t)grow * F + c4 * 4);
        if (APPLY_ELU) {
            v.x = elu_act(v.x + bias[c4 * 4 + 0]);
            v.y = elu_act(v.y + bias[c4 * 4 + 1]);
            v.z = elu_act(v.z + bias[c4 * 4 + 2]);
            v.w = elu_act(v.w + bias[c4 * 4 + 3]);
        }
        *(float4*)&sA[r][c4 * 4] = v;
    }
    __syncthreads();

    float acc[8][4] = {};
    const float4* __restrict__ Wv = (const float4*)W;

    #pragma unroll 4
    for (int k = 0; k < F; k++) {
        float4 b = __ldg(&Wv[k * 32 + tidx]);   // W[k][tidx*4..+3], L1-hot
        #pragma unroll
        for (int i = 0; i < 8; i++) {
            float a = sA[tidy * 8 + i][k];      // warp-broadcast LDS
            acc[i][0] += a * b.x;
            acc[i][1] += a * b.y;
            acc[i][2] += a * b.z;
            acc[i][3] += a * b.w;
        }
    }

    #pragma unroll
    for (int i = 0; i < 8; i++) {
        int grow = rowBase + tidy * 8 + i;
        if (grow < n)
            *(float4*)(g_tmp + (size_t)grow * F + tidx * 4) =
                make_float4(acc[i][0], acc[i][1], acc[i][2], acc[i][3]);
    }
}

// ---------------- agg init: self-loop term agg[n] = dis[n]^2 * tmp[n] -------
__global__ void init_agg_kernel(int n) {
    int idx = blockIdx.x * blockDim.x + threadIdx.x;   // float4 index
    if (idx >= n * (F / 4)) return;
    int node = idx >> 5;                                // /(F/4)
    float w = g_dis[node];
    w *= w;
    float4 v = ((const float4*)g_tmp)[idx];
    v.x *= w; v.y *= w; v.z *= w; v.w *= w;
    ((float4*)g_agg)[idx] = v;
}

// ---------------- edge scatter: agg[dst] += dis[s]*dis[d] * tmp[src] --------
// One warp per edge: lane -> one float4 (32*16B = full 512B row).
__global__ __launch_bounds__(256) void scatter_kernel(
    const int* __restrict__ ei, int E)
{
    int g = blockIdx.x * blockDim.x + threadIdx.x;
    int e = g >> 5;
    int lane = g & 31;
    if (e >= E) return;

    int s = __ldg(ei + e);
    int d = __ldg(ei + E + e);
    float w = __ldg(g_dis + s) * __ldg(g_dis + d);

    float4 v = *(const float4*)(g_tmp + (size_t)s * F + lane * 4);
    v.x *= w; v.y *= w; v.z *= w; v.w *= w;

    float* p = g_agg + (size_t)d * F + lane * 4;
    asm volatile("red.global.add.v4.f32 [%0], {%1, %2, %3, %4};"
                 :: "l"(p), "f"(v.x), "f"(v.y), "f"(v.z), "f"(v.w)
                 : "memory");
}

// ---------------- final head: out[n] = elu(agg[n]+b2) . Wl + bl -------------
__global__ __launch_bounds__(256) void final_kernel(
    const float* __restrict__ bias,  // bs[2]
    const float* __restrict__ Wl,    // [128]
    const float* __restrict__ bl,    // [1]
    float* __restrict__ out, int n)
{
    int g = blockIdx.x * blockDim.x + threadIdx.x;
    int node = g >> 5;
    int lane = g & 31;
    if (node >= n) return;

    float4 v  = *(const float4*)(g_agg + (size_t)node * F + lane * 4);
    float4 bb = *(const float4*)(bias + lane * 4);
    float4 w  = *(const float4*)(Wl + lane * 4);

    float s = elu_act(v.x + bb.x) * w.x
            + elu_act(v.y + bb.y) * w.y
            + elu_act(v.z + bb.z) * w.z
            + elu_act(v.w + bb.w) * w.w;

    #pragma unroll
    for (int o = 16; o > 0; o >>= 1)
        s += __shfl_xor_sync(0xFFFFFFFFu, s, o);

    if (lane == 0) out[node] = s + bl[0];
}

// ---------------- launch ----------------------------------------------------
extern "C" void kernel_launch(void* const* d_in, const int* in_sizes, int n_in,
                              void* d_out, int out_size)
{
    const float* x   = (const float*)d_in[0];   // [N,128]
    const float* Ws  = (const float*)d_in[1];   // [3,128,128]
    const float* bs  = (const float*)d_in[2];   // [3,128]
    const float* Wl  = (const float*)d_in[3];   // [128,1]
    const float* bl  = (const float*)d_in[4];   // [1]
    const int*   ei  = (const int*)d_in[5];     // [2,E]
    float* out = (float*)d_out;

    int n = in_sizes[0] / F;
    int E = in_sizes[5] / 2;
    if (n > NN) n = NN;
    if (E > EE) E = EE;

    const int TB = 256;

    // degree + normalization (self-loops folded as deg init = 1)
    init_deg_kernel<<<(n + TB - 1) / TB, TB>>>(n);
    count_deg_kernel<<<(E + TB - 1) / TB, TB>>>(ei, E);
    dis_kernel<<<(n + TB - 1) / TB, TB>>>(n);

    int gemmGrid    = (n + 63) / 64;
    int aggGrid     = (n * (F / 4) + TB - 1) / TB;
    long long sth   = (long long)E * 32;
    int scatGrid    = (int)((sth + TB - 1) / TB);
    long long fth   = (long long)n * 32;
    int finalGrid   = (int)((fth + TB - 1) / TB);

    // layer 0: A = x, no activation on input
    gemm_kernel<false><<<gemmGrid, TB>>>(x, Ws + 0 * F * F, nullptr, n);
    init_agg_kernel<<<aggGrid, TB>>>(n);
    scatter_kernel<<<scatGrid, TB>>>(ei, E);

    // layer 1: A = elu(agg + bs[0])
    gemm_kernel<true><<<gemmGrid, TB>>>(nullptr, Ws + 1 * F * F, bs + 0 * F, n);
    init_agg_kernel<<<aggGrid, TB>>>(n);
    scatter_kernel<<<scatGrid, TB>>>(ei, E);

    // layer 2: A = elu(agg + bs[1])
    gemm_kernel<true><<<gemmGrid, TB>>>(nullptr, Ws + 2 * F * F, bs + 1 * F, n);
    init_agg_kernel<<<aggGrid, TB>>>(n);
    scatter_kernel<<<scatGrid, TB>>>(ei, E);

    // head: out = elu(agg + bs[2]) @ Wl + bl
    final_kernel<<<finalGrid, TB>>>(bs + 2 * F, Wl, bl, out, n);
}

// round 6
// speedup vs baseline: 1.0554x; 1.0554x over previous
#include <cuda_runtime.h>
#include <cuda_bf16.h>
#include <cstdint>

// Problem constants (compile-time for __device__ scratch sizing)
constexpr int NN = 50000;   // nodes
constexpr int EE = 800000;  // edges
constexpr int F  = 128;     // feature dim

// ---------------- scratch (device globals; no allocation allowed) -----------
__device__ float g_tmp[NN * F];     // tmp' = dis[row] * (A @ W)
__device__ float g_agg[NN * F];     // raw aggregation (pre dis[dst] scaling)
__device__ float g_dis[NN];         // deg^{-1/2}
__device__ int   g_cnt[NN];         // in-edge count (excl. self loop)
__device__ int   g_rowstart[NN];    // CSR row offsets (exclusive scan of cnt)
__device__ int   g_cursor[NN];      // fill cursors
__device__ int   g_csrc[EE];        // CSR src indices grouped by dst

// ---------------- degree / normalization / CSR build ------------------------
__global__ void init_cnt_kernel(int n) {
    int i = blockIdx.x * blockDim.x + threadIdx.x;
    if (i < n) g_cnt[i] = 0;
}

__global__ void count_kernel(const int* __restrict__ ei, int E) {
    int e = blockIdx.x * blockDim.x + threadIdx.x;
    if (e < E) atomicAdd(&g_cnt[ei[E + e]], 1);   // dst = ei[1][e]
}

__global__ void dis_kernel(int n) {
    int i = blockIdx.x * blockDim.x + threadIdx.x;
    if (i < n) g_dis[i] = rsqrtf(1.0f + (float)g_cnt[i]);  // +1 = self-loop
}

// Single-block exclusive scan of g_cnt -> g_rowstart (and g_cursor copy).
__global__ void scan_kernel(int n) {
    __shared__ int warpsum[32];
    __shared__ int carry;
    int tid = threadIdx.x, lane = tid & 31, wid = tid >> 5;
    if (tid == 0) carry = 0;
    __syncthreads();

    for (int chunk = 0; chunk < n; chunk += 1024) {
        int i = chunk + tid;
        int v = (i < n) ? g_cnt[i] : 0;
        // inclusive warp scan
        int x = v;
        #pragma unroll
        for (int o = 1; o < 32; o <<= 1) {
            int y = __shfl_up_sync(0xFFFFFFFFu, x, o);
            if (lane >= o) x += y;
        }
        if (lane == 31) warpsum[wid] = x;
        __syncthreads();
        if (wid == 0) {
            int w = warpsum[lane];
            #pragma unroll
            for (int o = 1; o < 32; o <<= 1) {
                int y = __shfl_up_sync(0xFFFFFFFFu, w, o);
                if (lane >= o) w += y;
            }
            warpsum[lane] = w;   // inclusive scan of warp sums
        }
        __syncthreads();
        int excl = (x - v) + (wid ? warpsum[wid - 1] : 0) + carry;
        if (i < n) { g_rowstart[i] = excl; g_cursor[i] = excl; }
        __syncthreads();
        if (tid == 0) carry += warpsum[31];
        __syncthreads();
    }
}

__global__ void fill_kernel(const int* __restrict__ ei, int E) {
    int e = blockIdx.x * blockDim.x + threadIdx.x;
    if (e >= E) return;
    int s = ei[e];
    int d = ei[E + e];
    int pos = atomicAdd(&g_cursor[d], 1);
    g_csrc[pos] = s;
}

// ---------------- GEMM: tmp' = dis * (act(A) @ W) ----------------------------
// BM=64 rows per CTA, 256 threads, thread -> 8 rows x 4 cols.
// Inner loop steps k by 4: 4x LDG.128 (W, L1-hot) + 8x broadcast LDS.128 (A)
// + 128 FFMA. ELU(dis*agg + bias) of the PREVIOUS layer fused into A load.
__device__ __forceinline__ float elu_act(float v) {
    return v > 0.0f ? v : expm1f(v);
}

template <bool APPLY_ELU>
__global__ __launch_bounds__(256) void gemm_kernel(
    const float* __restrict__ Ain,   // nullptr => read g_agg (raw)
    const float* __restrict__ W,     // [128,128] row-major (k-major)
    const float* __restrict__ bias,  // [128] prev-layer bias (ELU path)
    int n)
{
    constexpr int BM = 64;
    __shared__ float sA[BM][F];

    const float* __restrict__ A = Ain ? Ain : g_agg;

    int tid  = threadIdx.x;
    int tidx = tid & 31;   // column group (4 cols)
    int tidy = tid >> 5;   // row group (8 rows) == warp id
    int rowBase = blockIdx.x * BM;

    // Load A tile: 64*128 floats = 2048 float4 slots, 8 per thread.
    #pragma unroll
    for (int t = 0; t < 8; t++) {
        int idx = t * 256 + tid;   // float4 slot
        int r   = idx >> 5;
        int c4  = idx & 31;
        int grow = rowBase + r;
        float4 v = make_float4(0.f, 0.f, 0.f, 0.f);
        if (grow < n) {
            v = *(const float4*)(A + (size_t)grow * F + c4 * 4);
            if (APPLY_ELU) {
                float dw = g_dis[grow];   // residual dis[dst] factor
                v.x = elu_act(v.x * dw + bias[c4 * 4 + 0]);
                v.y = elu_act(v.y * dw + bias[c4 * 4 + 1]);
                v.z = elu_act(v.z * dw + bias[c4 * 4 + 2]);
                v.w = elu_act(v.w * dw + bias[c4 * 4 + 3]);
            }
        }
        *(float4*)&sA[r][c4 * 4] = v;
    }
    __syncthreads();

    float acc[8][4] = {};
    const float4* __restrict__ Wv = (const float4*)W;

    #pragma unroll 2
    for (int k = 0; k < F; k += 4) {
        float4 b0 = __ldg(&Wv[(k + 0) * 32 + tidx]);
        float4 b1 = __ldg(&Wv[(k + 1) * 32 + tidx]);
        float4 b2 = __ldg(&Wv[(k + 2) * 32 + tidx]);
        float4 b3 = __ldg(&Wv[(k + 3) * 32 + tidx]);
        #pragma unroll
        for (int i = 0; i < 8; i++) {
            float4 a = *(const float4*)&sA[tidy * 8 + i][k];  // warp broadcast
            acc[i][0] += a.x * b0.x; acc[i][1] += a.x * b0.y;
            acc[i][2] += a.x * b0.z; acc[i][3] += a.x * b0.w;
            acc[i][0] += a.y * b1.x; acc[i][1] += a.y * b1.y;
            acc[i][2] += a.y * b1.z; acc[i][3] += a.y * b1.w;
            acc[i][0] += a.z * b2.x; acc[i][1] += a.z * b2.y;
            acc[i][2] += a.z * b2.z; acc[i][3] += a.z * b2.w;
            acc[i][0] += a.w * b3.x; acc[i][1] += a.w * b3.y;
            acc[i][2] += a.w * b3.z; acc[i][3] += a.w * b3.w;
        }
    }

    // Epilogue: tmp' = dis[row] * acc
    #pragma unroll
    for (int i = 0; i < 8; i++) {
        int grow = rowBase + tidy * 8 + i;
        if (grow < n) {
            float dw = g_dis[grow];
            *(float4*)(g_tmp + (size_t)grow * F + tidx * 4) =
                make_float4(acc[i][0] * dw, acc[i][1] * dw,
                            acc[i][2] * dw, acc[i][3] * dw);
        }
    }
}

// ---------------- propagate: agg_raw[d] = tmp'[d] + sum_{(s,d) in E} tmp'[s] --
// One warp per dst node: gather its src rows (CSR), accumulate in registers,
// store the row ONCE (no atomics).
__global__ __launch_bounds__(256) void propagate_kernel(int n)
{
    int warpId = blockIdx.x * 8 + (threadIdx.x >> 5);
    int lane   = threadIdx.x & 31;
    if (warpId >= n) return;

    int beg = g_rowstart[warpId];
    int cnt = g_cnt[warpId];

    // self-loop term
    float4 acc = __ldg((const float4*)(g_tmp + (size_t)warpId * F) + lane);

    int j = 0;
    for (; j + 1 < cnt; j += 2) {
        int s0 = __ldg(&g_csrc[beg + j]);
        int s1 = __ldg(&g_csrc[beg + j + 1]);
        float4 v0 = __ldg((const float4*)(g_tmp + (size_t)s0 * F) + lane);
        float4 v1 = __ldg((const float4*)(g_tmp + (size_t)s1 * F) + lane);
        acc.x += v0.x; acc.y += v0.y; acc.z += v0.z; acc.w += v0.w;
        acc.x += v1.x; acc.y += v1.y; acc.z += v1.z; acc.w += v1.w;
    }
    if (j < cnt) {
        int s0 = __ldg(&g_csrc[beg + j]);
        float4 v0 = __ldg((const float4*)(g_tmp + (size_t)s0 * F) + lane);
        acc.x += v0.x; acc.y += v0.y; acc.z += v0.z; acc.w += v0.w;
    }

    ((float4*)(g_agg + (size_t)warpId * F))[lane] = acc;
}

// ---------------- final head: out[n] = elu(dis*agg + b2) . Wl + bl ----------
__global__ __launch_bounds__(256) void final_kernel(
    const float* __restrict__ bias,  // bs[2]
    const float* __restrict__ Wl,    // [128]
    const float* __restrict__ bl,    // [1]
    float* __restrict__ out, int n)
{
    int g = blockIdx.x * blockDim.x + threadIdx.x;
    int node = g >> 5;
    int lane = g & 31;
    if (node >= n) return;

    float dw  = g_dis[node];
    float4 v  = *(const float4*)(g_agg + (size_t)node * F + lane * 4);
    float4 bb = *(const float4*)(bias + lane * 4);
    float4 w  = *(const float4*)(Wl + lane * 4);

    float s = elu_act(v.x * dw + bb.x) * w.x
            + elu_act(v.y * dw + bb.y) * w.y
            + elu_act(v.z * dw + bb.z) * w.z
            + elu_act(v.w * dw + bb.w) * w.w;

    #pragma unroll
    for (int o = 16; o > 0; o >>= 1)
        s += __shfl_xor_sync(0xFFFFFFFFu, s, o);

    if (lane == 0) out[node] = s + bl[0];
}

// ---------------- launch ----------------------------------------------------
extern "C" void kernel_launch(void* const* d_in, const int* in_sizes, int n_in,
                              void* d_out, int out_size)
{
    const float* x   = (const float*)d_in[0];   // [N,128]
    const float* Ws  = (const float*)d_in[1];   // [3,128,128]
    const float* bs  = (const float*)d_in[2];   // [3,128]
    const float* Wl  = (const float*)d_in[3];   // [128,1]
    const float* bl  = (const float*)d_in[4];   // [1]
    const int*   ei  = (const int*)d_in[5];     // [2,E]
    float* out = (float*)d_out;

    int n = in_sizes[0] / F;
    int E = in_sizes[5] / 2;
    if (n > NN) n = NN;
    if (E > EE) E = EE;

    const int TB = 256;

    // CSR build + normalization (self-loops folded analytically)
    init_cnt_kernel<<<(n + TB - 1) / TB, TB>>>(n);
    count_kernel<<<(E + TB - 1) / TB, TB>>>(ei, E);
    dis_kernel<<<(n + TB - 1) / TB, TB>>>(n);
    scan_kernel<<<1, 1024>>>(n);
    fill_kernel<<<(E + TB - 1) / TB, TB>>>(ei, E);

    int gemmGrid  = (n + 63) / 64;
    int propGrid  = (n + 7) / 8;                 // 8 warps per CTA
    long long fth = (long long)n * 32;
    int finalGrid = (int)((fth + TB - 1) / TB);

    // layer 0: A = x (no activation)
    gemm_kernel<false><<<gemmGrid, TB>>>(x, Ws + 0 * F * F, nullptr, n);
    propagate_kernel<<<propGrid, TB>>>(n);

    // layer 1: A = elu(dis*agg + bs[0])
    gemm_kernel<true><<<gemmGrid, TB>>>(nullptr, Ws + 1 * F * F, bs + 0 * F, n);
    propagate_kernel<<<propGrid, TB>>>(n);

    // layer 2: A = elu(dis*agg + bs[1])
    gemm_kernel<true><<<gemmGrid, TB>>>(nullptr, Ws + 2 * F * F, bs + 1 * F, n);
    propagate_kernel<<<propGrid, TB>>>(n);

    // head
    final_kernel<<<finalGrid, TB>>>(bs + 2 * F, Wl, bl, out, n);
}

// round 7
// speedup vs baseline: 1.6924x; 1.6036x over previous
#include <cuda_runtime.h>
#include <cuda_bf16.h>
#include <cstdint>

// Problem constants (compile-time for __device__ scratch sizing)
constexpr int NN = 50000;   // nodes
constexpr int EE = 800000;  // edges
constexpr int F  = 128;     // feature dim
constexpr int SCAN_B = 1024;               // elements per scan block
constexpr int SCAN_NBLK = (NN + SCAN_B - 1) / SCAN_B;   // 49

// ---------------- scratch (device globals; no allocation allowed) -----------
__device__ float g_tmp[NN * F];     // tmp' = dis[row] * (A @ W)
__device__ float g_agg[NN * F];     // raw aggregation (pre dis[dst] scaling)
__device__ float g_dis[NN];         // deg^{-1/2}
__device__ int   g_cnt[NN];         // in-edge count (excl. self loop)
__device__ int   g_rowstart[NN];    // CSR row offsets (exclusive scan of cnt)
__device__ int   g_cursor[NN];      // fill cursors
__device__ int   g_csrc[EE];        // CSR src indices grouped by dst
__device__ int   g_blocksum[256];   // per-block scan totals
__device__ int   g_blockoff[256];   // exclusive scan of block totals

// ---------------- degree / CSR build ----------------------------------------
__global__ void init_cnt_kernel(int n) {
    int i = blockIdx.x * blockDim.x + threadIdx.x;
    if (i < n) g_cnt[i] = 0;
}

__global__ void count_kernel(const int* __restrict__ ei, int E) {
    int e = blockIdx.x * blockDim.x + threadIdx.x;
    if (e < E) atomicAdd(&g_cnt[ei[E + e]], 1);   // dst = ei[1][e]
}

// Pass 1: per-block exclusive scan of g_cnt into g_rowstart (block-local),
// block totals into g_blocksum. Also computes dis = rsqrt(1+cnt).
__global__ __launch_bounds__(SCAN_B) void scan_blocks_kernel(int n) {
    __shared__ int warpsum[32];
    int tid = threadIdx.x, lane = tid & 31, wid = tid >> 5;
    int i = blockIdx.x * SCAN_B + tid;
    int v = (i < n) ? g_cnt[i] : 0;
    if (i < n) g_dis[i] = rsqrtf(1.0f + (float)v);   // self-loop folded

    // inclusive warp scan
    int x = v;
    #pragma unroll
    for (int o = 1; o < 32; o <<= 1) {
        int y = __shfl_up_sync(0xFFFFFFFFu, x, o);
        if (lane >= o) x += y;
    }
    if (lane == 31) warpsum[wid] = x;
    __syncthreads();
    if (wid == 0) {
        int w = warpsum[lane];
        #pragma unroll
        for (int o = 1; o < 32; o <<= 1) {
            int y = __shfl_up_sync(0xFFFFFFFFu, w, o);
            if (lane >= o) w += y;
        }
        warpsum[lane] = w;   // inclusive scan of warp sums
    }
    __syncthreads();
    int excl = (x - v) + (wid ? warpsum[wid - 1] : 0);
    if (i < n) g_rowstart[i] = excl;
    if (tid == SCAN_B - 1) g_blocksum[blockIdx.x] = warpsum[31];
}

// Pass 2: single small block scans the <=256 block totals (exclusive).
__global__ __launch_bounds__(256) void scan_sums_kernel(int nblk) {
    __shared__ int warpsum[8];
    int tid = threadIdx.x, lane = tid & 31, wid = tid >> 5;
    int v = (tid < nblk) ? g_blocksum[tid] : 0;
    int x = v;
    #pragma unroll
    for (int o = 1; o < 32; o <<= 1) {
        int y = __shfl_up_sync(0xFFFFFFFFu, x, o);
        if (lane >= o) x += y;
    }
    if (lane == 31) warpsum[wid] = x;
    __syncthreads();
    int woff = 0;
    for (int w = 0; w < wid; w++) woff += warpsum[w];
    if (tid < nblk) g_blockoff[tid] = (x - v) + woff;
}

// Pass 3: add block offsets; init cursors.
__global__ __launch_bounds__(SCAN_B) void scan_add_kernel(int n) {
    int i = blockIdx.x * SCAN_B + threadIdx.x;
    if (i >= n) return;
    int r = g_rowstart[i] + g_blockoff[blockIdx.x];
    g_rowstart[i] = r;
    g_cursor[i] = r;
}

__global__ void fill_kernel(const int* __restrict__ ei, int E) {
    int e = blockIdx.x * blockDim.x + threadIdx.x;
    if (e >= E) return;
    int s = ei[e];
    int d = ei[E + e];
    int pos = atomicAdd(&g_cursor[d], 1);
    g_csrc[pos] = s;
}

// ---------------- GEMM: tmp' = dis * (act(A) @ W) ----------------------------
// BM=64 rows per CTA, 256 threads, thread -> 8 rows x 4 cols.
// Inner loop steps k by 4: 4x LDG.128 (W, L1-hot) + 8x broadcast LDS.128 (A)
// + 128 FFMA. ELU(dis*agg + bias) of the PREVIOUS layer fused into A load.
__device__ __forceinline__ float elu_act(float v) {
    return v > 0.0f ? v : expm1f(v);
}

template <bool APPLY_ELU>
__global__ __launch_bounds__(256) void gemm_kernel(
    const float* __restrict__ Ain,   // nullptr => read g_agg (raw)
    const float* __restrict__ W,     // [128,128] row-major (k-major)
    const float* __restrict__ bias,  // [128] prev-layer bias (ELU path)
    int n)
{
    constexpr int BM = 64;
    __shared__ float sA[BM][F];

    const float* __restrict__ A = Ain ? Ain : g_agg;

    int tid  = threadIdx.x;
    int tidx = tid & 31;   // column group (4 cols)
    int tidy = tid >> 5;   // row group (8 rows) == warp id
    int rowBase = blockIdx.x * BM;

    // Load A tile: 64*128 floats = 2048 float4 slots, 8 per thread.
    #pragma unroll
    for (int t = 0; t < 8; t++) {
        int idx = t * 256 + tid;   // float4 slot
        int r   = idx >> 5;
        int c4  = idx & 31;
        int grow = rowBase + r;
        float4 v = make_float4(0.f, 0.f, 0.f, 0.f);
        if (grow < n) {
            v = *(const float4*)(A + (size_t)grow * F + c4 * 4);
            if (APPLY_ELU) {
                float dw = g_dis[grow];   // residual dis[dst] factor
                v.x = elu_act(v.x * dw + bias[c4 * 4 + 0]);
                v.y = elu_act(v.y * dw + bias[c4 * 4 + 1]);
                v.z = elu_act(v.z * dw + bias[c4 * 4 + 2]);
                v.w = elu_act(v.w * dw + bias[c4 * 4 + 3]);
            }
        }
        *(float4*)&sA[r][c4 * 4] = v;
    }
    __syncthreads();

    float acc[8][4] = {};
    const float4* __restrict__ Wv = (const float4*)W;

    #pragma unroll 2
    for (int k = 0; k < F; k += 4) {
        float4 b0 = __ldg(&Wv[(k + 0) * 32 + tidx]);
        float4 b1 = __ldg(&Wv[(k + 1) * 32 + tidx]);
        float4 b2 = __ldg(&Wv[(k + 2) * 32 + tidx]);
        float4 b3 = __ldg(&Wv[(k + 3) * 32 + tidx]);
        #pragma unroll
        for (int i = 0; i < 8; i++) {
            float4 a = *(const float4*)&sA[tidy * 8 + i][k];  // warp broadcast
            acc[i][0] += a.x * b0.x; acc[i][1] += a.x * b0.y;
            acc[i][2] += a.x * b0.z; acc[i][3] += a.x * b0.w;
            acc[i][0] += a.y * b1.x; acc[i][1] += a.y * b1.y;
            acc[i][2] += a.y * b1.z; acc[i][3] += a.y * b1.w;
            acc[i][0] += a.z * b2.x; acc[i][1] += a.z * b2.y;
            acc[i][2] += a.z * b2.z; acc[i][3] += a.z * b2.w;
            acc[i][0] += a.w * b3.x; acc[i][1] += a.w * b3.y;
            acc[i][2] += a.w * b3.z; acc[i][3] += a.w * b3.w;
        }
    }

    // Epilogue: tmp' = dis[row] * acc
    #pragma unroll
    for (int i = 0; i < 8; i++) {
        int grow = rowBase + tidy * 8 + i;
        if (grow < n) {
            float dw = g_dis[grow];
            *(float4*)(g_tmp + (size_t)grow * F + tidx * 4) =
                make_float4(acc[i][0] * dw, acc[i][1] * dw,
                            acc[i][2] * dw, acc[i][3] * dw);
        }
    }
}

// ---------------- propagate: agg_raw[d] = tmp'[d] + sum_{(s,d) in E} tmp'[s] --
// One warp per dst node: gather its src rows (CSR), accumulate in registers,
// store the row ONCE (no atomics). Unrolled x4 with 2 independent
// accumulators to keep >=4 row-gathers in flight per warp.
__global__ __launch_bounds__(256) void propagate_kernel(int n)
{
    int warpId = blockIdx.x * 8 + (threadIdx.x >> 5);
    int lane   = threadIdx.x & 31;
    if (warpId >= n) return;

    int beg = g_rowstart[warpId];
    int cnt = g_cnt[warpId];

    // self-loop term
    float4 accA = __ldg((const float4*)(g_tmp + (size_t)warpId * F) + lane);
    float4 accB = make_float4(0.f, 0.f, 0.f, 0.f);

    int j = 0;
    for (; j + 3 < cnt; j += 4) {
        int s0 = __ldg(&g_csrc[beg + j + 0]);
        int s1 = __ldg(&g_csrc[beg + j + 1]);
        int s2 = __ldg(&g_csrc[beg + j + 2]);
        int s3 = __ldg(&g_csrc[beg + j + 3]);
        float4 v0 = __ldg((const float4*)(g_tmp + (size_t)s0 * F) + lane);
        float4 v1 = __ldg((const float4*)(g_tmp + (size_t)s1 * F) + lane);
        float4 v2 = __ldg((const float4*)(g_tmp + (size_t)s2 * F) + lane);
        float4 v3 = __ldg((const float4*)(g_tmp + (size_t)s3 * F) + lane);
        accA.x += v0.x; accA.y += v0.y; accA.z += v0.z; accA.w += v0.w;
        accB.x += v1.x; accB.y += v1.y; accB.z += v1.z; accB.w += v1.w;
        accA.x += v2.x; accA.y += v2.y; accA.z += v2.z; accA.w += v2.w;
        accB.x += v3.x; accB.y += v3.y; accB.z += v3.z; accB.w += v3.w;
    }
    for (; j < cnt; j++) {
        int s0 = __ldg(&g_csrc[beg + j]);
        float4 v0 = __ldg((const float4*)(g_tmp + (size_t)s0 * F) + lane);
        accA.x += v0.x; accA.y += v0.y; accA.z += v0.z; accA.w += v0.w;
    }

    accA.x += accB.x; accA.y += accB.y; accA.z += accB.z; accA.w += accB.w;
    ((float4*)(g_agg + (size_t)warpId * F))[lane] = accA;
}

// ---------------- final head: out[n] = elu(dis*agg + b2) . Wl + bl ----------
__global__ __launch_bounds__(256) void final_kernel(
    const float* __restrict__ bias,  // bs[2]
    const float* __restrict__ Wl,    // [128]
    const float* __restrict__ bl,    // [1]
    float* __restrict__ out, int n)
{
    int g = blockIdx.x * blockDim.x + threadIdx.x;
    int node = g >> 5;
    int lane = g & 31;
    if (node >= n) return;

    float dw  = g_dis[node];
    float4 v  = *(const float4*)(g_agg + (size_t)node * F + lane * 4);
    float4 bb = *(const float4*)(bias + lane * 4);
    float4 w  = *(const float4*)(Wl + lane * 4);

    float s = elu_act(v.x * dw + bb.x) * w.x
            + elu_act(v.y * dw + bb.y) * w.y
            + elu_act(v.z * dw + bb.z) * w.z
            + elu_act(v.w * dw + bb.w) * w.w;

    #pragma unroll
    for (int o = 16; o > 0; o >>= 1)
        s += __shfl_xor_sync(0xFFFFFFFFu, s, o);

    if (lane == 0) out[node] = s + bl[0];
}

// ---------------- launch ----------------------------------------------------
extern "C" void kernel_launch(void* const* d_in, const int* in_sizes, int n_in,
                              void* d_out, int out_size)
{
    const float* x   = (const float*)d_in[0];   // [N,128]
    const float* Ws  = (const float*)d_in[1];   // [3,128,128]
    const float* bs  = (const float*)d_in[2];   // [3,128]
    const float* Wl  = (const float*)d_in[3];   // [128,1]
    const float* bl  = (const float*)d_in[4];   // [1]
    const int*   ei  = (const int*)d_in[5];     // [2,E]
    float* out = (float*)d_out;

    int n = in_sizes[0] / F;
    int E = in_sizes[5] / 2;
    if (n > NN) n = NN;
    if (E > EE) E = EE;

    const int TB = 256;
    int nScanBlk = (n + SCAN_B - 1) / SCAN_B;   // <= 256 guaranteed for NN

    // CSR build + normalization (self-loops folded analytically)
    init_cnt_kernel<<<(n + TB - 1) / TB, TB>>>(n);
    count_kernel<<<(E + TB - 1) / TB, TB>>>(ei, E);
    scan_blocks_kernel<<<nScanBlk, SCAN_B>>>(n);    // also computes g_dis
    scan_sums_kernel<<<1, 256>>>(nScanBlk);
    scan_add_kernel<<<nScanBlk, SCAN_B>>>(n);
    fill_kernel<<<(E + TB - 1) / TB, TB>>>(ei, E);

    int gemmGrid  = (n + 63) / 64;
    int propGrid  = (n + 7) / 8;                 // 8 warps per CTA
    long long fth = (long long)n * 32;
    int finalGrid = (int)((fth + TB - 1) / TB);

    // layer 0: A = x (no activation)
    gemm_kernel<false><<<gemmGrid, TB>>>(x, Ws + 0 * F * F, nullptr, n);
    propagate_kernel<<<propGrid, TB>>>(n);

    // layer 1: A = elu(dis*agg + bs[0])
    gemm_kernel<true><<<gemmGrid, TB>>>(nullptr, Ws + 1 * F * F, bs + 0 * F, n);
    propagate_kernel<<<propGrid, TB>>>(n);

    // layer 2: A = elu(dis*agg + bs[1])
    gemm_kernel<true><<<gemmGrid, TB>>>(nullptr, Ws + 2 * F * F, bs + 1 * F, n);
    propagate_kernel<<<propGrid, TB>>>(n);

    // head
    final_kernel<<<finalGrid, TB>>>(bs + 2 * F, Wl, bl, out, n);
}

// round 12
// speedup vs baseline: 1.9018x; 1.1238x over previous
#include <cuda_runtime.h>
#include <cuda_bf16.h>
#include <cstdint>

// Problem constants (compile-time for __device__ scratch sizing)
constexpr int NN = 50000;   // nodes
constexpr int EE = 800000;  // edges
constexpr int F  = 128;     // feature dim
constexpr int SCAN_B = 1024;

// ---------------- scratch (device globals; no allocation allowed) -----------
__device__ float g_tmp[NN * F];     // tmp' = dis[row] * (A @ W)
__device__ float g_agg[NN * F];     // raw aggregation (pre dis[dst] scaling)
__device__ float g_dis[NN];         // deg^{-1/2}
__device__ int   g_cnt[NN];         // in-edge count (excl. self loop)
__device__ int   g_rowstart[NN];    // CSR row offsets
__device__ int   g_cursor[NN];      // fill cursors
__device__ int   g_csrc[EE];        // CSR src indices grouped by dst
__device__ int   g_blocksum[256];
__device__ int   g_blockoff[256];
// W in mma.sync B-fragment layout: [layer][0=hi,1=lo][kstep][ntile][lane]
// lane's uint2 = {k=(lane&3)*2,+1 ; k+8,+9} at n = ntile*8 + (lane>>2), packed bf16x2.
__device__ uint2 g_wfrag[3][2][8][16][32];

// ---------------- degree / CSR build ----------------------------------------
__global__ void init_cnt_kernel(int n) {
    int i = blockIdx.x * blockDim.x + threadIdx.x;
    if (i < n) g_cnt[i] = 0;
}

__global__ void count_kernel(const int* __restrict__ ei, int E) {
    int e = blockIdx.x * blockDim.x + threadIdx.x;
    if (e < E) atomicAdd(&g_cnt[ei[E + e]], 1);
}

__global__ __launch_bounds__(SCAN_B) void scan_blocks_kernel(int n) {
    __shared__ int warpsum[32];
    int tid = threadIdx.x, lane = tid & 31, wid = tid >> 5;
    int i = blockIdx.x * SCAN_B + tid;
    int v = (i < n) ? g_cnt[i] : 0;
    if (i < n) g_dis[i] = rsqrtf(1.0f + (float)v);

    int x = v;
    #pragma unroll
    for (int o = 1; o < 32; o <<= 1) {
        int y = __shfl_up_sync(0xFFFFFFFFu, x, o);
        if (lane >= o) x += y;
    }
    if (lane == 31) warpsum[wid] = x;
    __syncthreads();
    if (wid == 0) {
        int w = warpsum[lane];
        #pragma unroll
        for (int o = 1; o < 32; o <<= 1) {
            int y = __shfl_up_sync(0xFFFFFFFFu, w, o);
            if (lane >= o) w += y;
        }
        warpsum[lane] = w;
    }
    __syncthreads();
    int excl = (x - v) + (wid ? warpsum[wid - 1] : 0);
    if (i < n) g_rowstart[i] = excl;
    if (tid == SCAN_B - 1) g_blocksum[blockIdx.x] = warpsum[31];
}

__global__ __launch_bounds__(256) void scan_sums_kernel(int nblk) {
    __shared__ int warpsum[8];
    int tid = threadIdx.x, lane = tid & 31, wid = tid >> 5;
    int v = (tid < nblk) ? g_blocksum[tid] : 0;
    int x = v;
    #pragma unroll
    for (int o = 1; o < 32; o <<= 1) {
        int y = __shfl_up_sync(0xFFFFFFFFu, x, o);
        if (lane >= o) x += y;
    }
    if (lane == 31) warpsum[wid] = x;
    __syncthreads();
    int woff = 0;
    for (int w = 0; w < wid; w++) woff += warpsum[w];
    if (tid < nblk) g_blockoff[tid] = (x - v) + woff;
}

__global__ __launch_bounds__(SCAN_B) void scan_add_kernel(int n) {
    int i = blockIdx.x * SCAN_B + threadIdx.x;
    if (i >= n) return;
    int r = g_rowstart[i] + g_blockoff[blockIdx.x];
    g_rowstart[i] = r;
    g_cursor[i] = r;
}

__global__ void fill_kernel(const int* __restrict__ ei, int E) {
    int e = blockIdx.x * blockDim.x + threadIdx.x;
    if (e >= E) return;
    int s = ei[e];
    int d = ei[E + e];
    int pos = atomicAdd(&g_cursor[d], 1);
    g_csrc[pos] = s;
}

// ---------------- W fragment pre-bake ----------------------------------------
__device__ __forceinline__ uint32_t pack_bf2(__nv_bfloat16 lo16, __nv_bfloat16 hi16) {
    __nv_bfloat162 p;
    p.x = lo16; p.y = hi16;
    return *(uint32_t*)&p;
}

__global__ void wfrag_kernel(const float* __restrict__ Ws) {
    int i = blockIdx.x * blockDim.x + threadIdx.x;   // over 3*2*8*16*32 = 24576
    if (i >= 3 * 2 * 8 * 16 * 32) return;
    int lane = i & 31; int t = i >> 5;
    int nt = t & 15; t >>= 4;
    int ks = t & 7;  t >>= 3;
    int termB = t & 1;
    int l = t >> 1;
    int nn = nt * 8 + (lane >> 2);

    uint32_t regs[2];
    #pragma unroll
    for (int r = 0; r < 2; r++) {
        int k = ks * 16 + (lane & 3) * 2 + r * 8;
        float w0 = Ws[l * F * F + k * F + nn];
        float w1 = Ws[l * F * F + (k + 1) * F + nn];
        __nv_bfloat16 h0 = __float2bfloat16(w0);
        __nv_bfloat16 h1 = __float2bfloat16(w1);
        __nv_bfloat16 v0, v1;
        if (termB == 0) { v0 = h0; v1 = h1; }
        else {
            v0 = __float2bfloat16(w0 - __bfloat162float(h0));
            v1 = __float2bfloat16(w1 - __bfloat162float(h1));
        }
        regs[r] = pack_bf2(v0, v1);
    }
    g_wfrag[l][termB][ks][nt][lane] = make_uint2(regs[0], regs[1]);
}

// ---------------- tensor-core GEMM: tmp' = dis * (act(A) @ W) ---------------
// mma.sync.m16n8k16 bf16, 3-term split precision (HH + HL + LH).
// CTA: BM=64 rows, 8 warps = 2(M) x 4(N); warp tile 32x32.
// A staged in smem hi/lo bf16, row stride 136 bf16 (272B) -> conflict-free
// ldmatrix (rows spaced 4 banks, 4-word rows tile all 32 banks).
constexpr int LDA = 136;   // smem row stride in bf16 units

__device__ __forceinline__ float elu_act(float v) {
    return v > 0.0f ? v : expm1f(v);
}

__device__ __forceinline__ uint32_t smem_u32(const void* p) {
    uint32_t a;
    asm("{ .reg .u64 t; cvta.to.shared.u64 t, %1; cvt.u32.u64 %0, t; }"
        : "=r"(a) : "l"(p));
    return a;
}

template <bool APPLY_ELU>
__global__ __launch_bounds__(256) void gemm_mma_kernel(
    const float* __restrict__ Ain,   // nullptr => read g_agg (raw)
    int layer,
    const float* __restrict__ bias,  // prev-layer bias (ELU path)
    int n)
{
    __shared__ __nv_bfloat16 sAhi[64 * LDA];
    __shared__ __nv_bfloat16 sAlo[64 * LDA];

    const float* __restrict__ A = Ain ? Ain : g_agg;
    int tid = threadIdx.x, lane = tid & 31, wid = tid >> 5;
    int rowBase = blockIdx.x * 64;

    // ---- stage A as split bf16: thread -> 1 row, 32-col segment ----
    {
        int row  = tid >> 2;
        int cseg = (tid & 3) * 32;
        int grow = rowBase + row;
        if (grow < n) {
            float dw = APPLY_ELU ? g_dis[grow] : 0.0f;
            const float4* src = (const float4*)(A + (size_t)grow * F + cseg);
            #pragma unroll
            for (int j = 0; j < 8; j++) {
                float4 v = src[j];
                if (APPLY_ELU) {
                    const float* bp = bias + cseg + j * 4;
                    v.x = elu_act(v.x * dw + bp[0]);
                    v.y = elu_act(v.y * dw + bp[1]);
                    v.z = elu_act(v.z * dw + bp[2]);
                    v.w = elu_act(v.w * dw + bp[3]);
                }
                __nv_bfloat16 hx = __float2bfloat16(v.x);
                __nv_bfloat16 hy = __float2bfloat16(v.y);
                __nv_bfloat16 hz = __float2bfloat16(v.z);
                __nv_bfloat16 hw = __float2bfloat16(v.w);
                uint2 hv, lv;
                hv.x = pack_bf2(hx, hy);
                hv.y = pack_bf2(hz, hw);
                lv.x = pack_bf2(__float2bfloat16(v.x - __bfloat162float(hx)),
                                __float2bfloat16(v.y - __bfloat162float(hy)));
                lv.y = pack_bf2(__float2bfloat16(v.z - __bfloat162float(hz)),
                                __float2bfloat16(v.w - __bfloat162float(hw)));
                *(uint2*)&sAhi[row * LDA + cseg + j * 4] = hv;
                *(uint2*)&sAlo[row * LDA + cseg + j * 4] = lv;
            }
        } else {
            uint2 z = make_uint2(0u, 0u);
            #pragma unroll
            for (int j = 0; j < 8; j++) {
                *(uint2*)&sAhi[row * LDA + cseg + j * 4] = z;
                *(uint2*)&sAlo[row * LDA + cseg + j * 4] = z;
            }
        }
    }
    __syncthreads();

    int mwarp = wid & 1;    // 0..1 : rows mwarp*32
    int nwarp = wid >> 1;   // 0..3 : cols nwarp*32

    float c[2][4][4];
    #pragma unroll
    for (int mt = 0; mt < 2; mt++)
        #pragma unroll
        for (int nt = 0; nt < 4; nt++)
            #pragma unroll
            for (int q = 0; q < 4; q++) c[mt][nt][q] = 0.0f;

    // ldmatrix per-lane source row/col within the 16x16 tile
    int lj   = lane >> 3;
    int lrow = (lj & 1) * 8 + (lane & 7);   // 0..15
    int lcol = (lj >> 1) * 8;               // 0 or 8

    #pragma unroll
    for (int term = 0; term < 3; term++) {
        const __nv_bfloat16* __restrict__ Asrc = (term == 2) ? sAlo : sAhi;
        const uint2* __restrict__ Bsrc = &g_wfrag[layer][term == 1][0][0][0];

        #pragma unroll
        for (int ks = 0; ks < 8; ks++) {
            uint32_t a[2][4];
            #pragma unroll
            for (int mt = 0; mt < 2; mt++) {
                uint32_t addr = smem_u32(
                    &Asrc[(mwarp * 32 + mt * 16 + lrow) * LDA + ks * 16 + lcol]);
                asm volatile(
                    "ldmatrix.sync.aligned.m8n8.x4.shared.b16 {%0,%1,%2,%3}, [%4];"
                    : "=r"(a[mt][0]), "=r"(a[mt][1]), "=r"(a[mt][2]), "=r"(a[mt][3])
                    : "r"(addr));
            }
            uint2 b[4];
            #pragma unroll
            for (int nt = 0; nt < 4; nt++)
                b[nt] = Bsrc[(ks * 16 + nwarp * 4 + nt) * 32 + lane];

            #pragma unroll
            for (int mt = 0; mt < 2; mt++)
                #pragma unroll
                for (int nt = 0; nt < 4; nt++)
                    asm volatile(
                        "mma.sync.aligned.m16n8k16.row.col.f32.bf16.bf16.f32 "
                        "{%0,%1,%2,%3}, {%4,%5,%6,%7}, {%8,%9}, {%0,%1,%2,%3};"
                        : "+f"(c[mt][nt][0]), "+f"(c[mt][nt][1]),
                          "+f"(c[mt][nt][2]), "+f"(c[mt][nt][3])
                        : "r"(a[mt][0]), "r"(a[mt][1]), "r"(a[mt][2]), "r"(a[mt][3]),
                          "r"(b[nt].x), "r"(b[nt].y));
        }
    }

    // ---- epilogue: tmp' = dis[row] * C ----
    int r0 = lane >> 2;
    int c0 = (lane & 3) * 2;
    #pragma unroll
    for (int mt = 0; mt < 2; mt++) {
        int row_a = rowBase + mwarp * 32 + mt * 16 + r0;
        int row_b = row_a + 8;
        float dwa = (row_a < n) ? g_dis[row_a] : 0.0f;
        float dwb = (row_b < n) ? g_dis[row_b] : 0.0f;
        #pragma unroll
        for (int nt = 0; nt < 4; nt++) {
            int col = nwarp * 32 + nt * 8 + c0;
            if (row_a < n)
                *(float2*)&g_tmp[(size_t)row_a * F + col] =
                    make_float2(c[mt][nt][0] * dwa, c[mt][nt][1] * dwa);
            if (row_b < n)
                *(float2*)&g_tmp[(size_t)row_b * F + col] =
                    make_float2(c[mt][nt][2] * dwb, c[mt][nt][3] * dwb);
        }
    }
}

// ---------------- propagate: agg_raw[d] = tmp'[d] + sum_{(s,d)} tmp'[s] ------
__global__ __launch_bounds__(256) void propagate_kernel(int n)
{
    int warpId = blockIdx.x * 8 + (threadIdx.x >> 5);
    int lane   = threadIdx.x & 31;
    if (warpId >= n) return;

    int beg = g_rowstart[warpId];
    int cnt = g_cnt[warpId];

    float4 accA = __ldg((const float4*)(g_tmp + (size_t)warpId * F) + lane);
    float4 accB = make_float4(0.f, 0.f, 0.f, 0.f);

    int j = 0;
    for (; j + 3 < cnt; j += 4) {
        int s0 = __ldg(&g_csrc[beg + j + 0]);
        int s1 = __ldg(&g_csrc[beg + j + 1]);
        int s2 = __ldg(&g_csrc[beg + j + 2]);
        int s3 = __ldg(&g_csrc[beg + j + 3]);
        float4 v0 = __ldg((const float4*)(g_tmp + (size_t)s0 * F) + lane);
        float4 v1 = __ldg((const float4*)(g_tmp + (size_t)s1 * F) + lane);
        float4 v2 = __ldg((const float4*)(g_tmp + (size_t)s2 * F) + lane);
        float4 v3 = __ldg((const float4*)(g_tmp + (size_t)s3 * F) + lane);
        accA.x += v0.x; accA.y += v0.y; accA.z += v0.z; accA.w += v0.w;
        accB.x += v1.x; accB.y += v1.y; accB.z += v1.z; accB.w += v1.w;
        accA.x += v2.x; accA.y += v2.y; accA.z += v2.z; accA.w += v2.w;
        accB.x += v3.x; accB.y += v3.y; accB.z += v3.z; accB.w += v3.w;
    }
    for (; j < cnt; j++) {
        int s0 = __ldg(&g_csrc[beg + j]);
        float4 v0 = __ldg((const float4*)(g_tmp + (size_t)s0 * F) + lane);
        accA.x += v0.x; accA.y += v0.y; accA.z += v0.z; accA.w += v0.w;
    }

    accA.x += accB.x; accA.y += accB.y; accA.z += accB.z; accA.w += accB.w;
    ((float4*)(g_agg + (size_t)warpId * F))[lane] = accA;
}

// ---------------- final head: out[n] = elu(dis*agg + b2) . Wl + bl ----------
__global__ __launch_bounds__(256) void final_kernel(
    const float* __restrict__ bias,
    const float* __restrict__ Wl,
    const float* __restrict__ bl,
    float* __restrict__ out, int n)
{
    int g = blockIdx.x * blockDim.x + threadIdx.x;
    int node = g >> 5;
    int lane = g & 31;
    if (node >= n) return;

    float dw  = g_dis[node];
    float4 v  = *(const float4*)(g_agg + (size_t)node * F + lane * 4);
    float4 bb = *(const float4*)(bias + lane * 4);
    float4 w  = *(const float4*)(Wl + lane * 4);

    float s = elu_act(v.x * dw + bb.x) * w.x
            + elu_act(v.y * dw + bb.y) * w.y
            + elu_act(v.z * dw + bb.z) * w.z
            + elu_act(v.w * dw + bb.w) * w.w;

    #pragma unroll
    for (int o = 16; o > 0; o >>= 1)
        s += __shfl_xor_sync(0xFFFFFFFFu, s, o);

    if (lane == 0) out[node] = s + bl[0];
}

// ---------------- launch ----------------------------------------------------
extern "C" void kernel_launch(void* const* d_in, const int* in_sizes, int n_in,
                              void* d_out, int out_size)
{
    const float* x   = (const float*)d_in[0];   // [N,128]
    const float* Ws  = (const float*)d_in[1];   // [3,128,128]
    const float* bs  = (const float*)d_in[2];   // [3,128]
    const float* Wl  = (const float*)d_in[3];   // [128,1]
    const float* bl  = (const float*)d_in[4];   // [1]
    const int*   ei  = (const int*)d_in[5];     // [2,E]
    float* out = (float*)d_out;

    int n = in_sizes[0] / F;
    int E = in_sizes[5] / 2;
    if (n > NN) n = NN;
    if (E > EE) E = EE;

    const int TB = 256;
    int nScanBlk = (n + SCAN_B - 1) / SCAN_B;

    // W fragment pre-bake + CSR build (self-loops folded analytically)
    wfrag_kernel<<<(3 * 2 * 8 * 16 * 32 + TB - 1) / TB, TB>>>(Ws);
    init_cnt_kernel<<<(n + TB - 1) / TB, TB>>>(n);
    count_kernel<<<(E + TB - 1) / TB, TB>>>(ei, E);
    scan_blocks_kernel<<<nScanBlk, SCAN_B>>>(n);    // also computes g_dis
    scan_sums_kernel<<<1, 256>>>(nScanBlk);
    scan_add_kernel<<<nScanBlk, SCAN_B>>>(n);
    fill_kernel<<<(E + TB - 1) / TB, TB>>>(ei, E);

    int gemmGrid  = (n + 63) / 64;
    int propGrid  = (n + 7) / 8;
    long long fth = (long long)n * 32;
    int finalGrid = (int)((fth + TB - 1) / TB);

    // layer 0: A = x (no activation)
    gemm_mma_kernel<false><<<gemmGrid, TB>>>(x, 0, nullptr, n);
    propagate_kernel<<<propGrid, TB>>>(n);

    // layer 1: A = elu(dis*agg + bs[0])
    gemm_mma_kernel<true><<<gemmGrid, TB>>>(nullptr, 1, bs + 0 * F, n);
    propagate_kernel<<<propGrid, TB>>>(n);

    // layer 2: A = elu(dis*agg + bs[1])
    gemm_mma_kernel<true><<<gemmGrid, TB>>>(nullptr, 2, bs + 1 * F, n);
    propagate_kernel<<<propGrid, TB>>>(n);

    // head
    final_kernel<<<finalGrid, TB>>>(bs + 2 * F, Wl, bl, out, n);
}